// round 6
// baseline (speedup 1.0000x reference)
#include <cuda_runtime.h>

// out[b, i] = x[b, i] * diagonal[i]
// x: [8192, 4096] f32, diagonal: [4096] f32, out: [8192, 4096] f32
//
// Persistent grid-stride kernel: 1184 CTAs (148 SMs x 8), each loops over
// contiguous 1024-float4 chunks. Single wave -> no wave transitions, and
// next-chunk loads overlap current-chunk stores (sustained MLP).

static constexpr int SIZE     = 4096;
static constexpr int BATCH    = 8192;
static constexpr int SIZE_V4  = SIZE / 4;                         // 1024
static constexpr long long TOTAL_V4 = (long long)SIZE * BATCH / 4; // 8,388,608
static constexpr int THREADS  = 256;
static constexpr int VPT      = 4;                                 // float4/thread/chunk
static constexpr int CHUNK_V4 = THREADS * VPT;                     // 1024
static constexpr int NCHUNKS  = (int)(TOTAL_V4 / CHUNK_V4);        // 8192, exact
static constexpr int GRID     = 148 * 8;                           // 1184

__global__ __launch_bounds__(THREADS)
void diag_scale_kernel(const float4* __restrict__ x,
                       const float4* __restrict__ diag,
                       float4* __restrict__ out)
{
    for (int chunk = blockIdx.x; chunk < NCHUNKS; chunk += GRID) {
        const long long base = (long long)chunk * CHUNK_V4 + threadIdx.x;

        // Front-batched independent loads: MLP = 4 within chunk,
        // and next chunk's loads overlap this chunk's stores.
        float4 xv[VPT];
#pragma unroll
        for (int k = 0; k < VPT; k++)
            xv[k] = __ldcs(&x[base + (long long)k * THREADS]);

#pragma unroll
        for (int k = 0; k < VPT; k++) {
            const long long i = base + (long long)k * THREADS;
            const float4 dv = __ldg(&diag[(int)(i & (SIZE_V4 - 1))]);
            float4 ov;
            ov.x = xv[k].x * dv.x;
            ov.y = xv[k].y * dv.y;
            ov.z = xv[k].z * dv.z;
            ov.w = xv[k].w * dv.w;
            __stcs(&out[i], ov);
        }
    }
}

extern "C" void kernel_launch(void* const* d_in, const int* in_sizes, int n_in,
                              void* d_out, int out_size)
{
    const float4* x    = (const float4*)d_in[0];
    const float4* diag = (const float4*)d_in[1];
    float4*       out  = (float4*)d_out;

    diag_scale_kernel<<<GRID, THREADS>>>(x, diag, out);
}

// round 7
// speedup vs baseline: 1.0471x; 1.0471x over previous
#include <cuda_runtime.h>

// out[b, i] = x[b, i] * diagonal[i]
// x: [8192, 4096] f32, diagonal: [4096] f32, out: [8192, 4096] f32
//
// Final-polish variant: 256-bit (v8) global accesses + column-stationary
// diagonal. Each thread owns ONE v8 column (diag loaded once into regs)
// and 2 consecutive rows, front-batched (512B in flight per thread).
//  - v8 halves L1tex wavefronts per byte vs float4
//  - diag-once removes all per-element diagonal loads
//  - ~34 regs -> ~75% occupancy

static constexpr int SIZE    = 4096;
static constexpr int BATCH   = 8192;
static constexpr int SIZE_V8 = SIZE / 8;                   // 512 v8 per row
static constexpr int THREADS = 256;
static constexpr int COL_CHUNKS = SIZE_V8 / THREADS;       // 2
static constexpr int ROWS_PER_THREAD = 2;
static constexpr int ROW_BLOCKS = BATCH / ROWS_PER_THREAD; // 4096

struct __align__(32) f8 { float v[8]; };

__device__ __forceinline__ f8 ldg256_cs(const f8* p) {
    f8 r;
    asm volatile("ld.global.cs.nc.v8.f32 {%0,%1,%2,%3,%4,%5,%6,%7}, [%8];"
                 : "=f"(r.v[0]), "=f"(r.v[1]), "=f"(r.v[2]), "=f"(r.v[3]),
                   "=f"(r.v[4]), "=f"(r.v[5]), "=f"(r.v[6]), "=f"(r.v[7])
                 : "l"(p));
    return r;
}

__device__ __forceinline__ void stg256_cs(f8* p, const f8& r) {
    asm volatile("st.global.cs.v8.f32 [%0], {%1,%2,%3,%4,%5,%6,%7,%8};"
                 :: "l"(p),
                    "f"(r.v[0]), "f"(r.v[1]), "f"(r.v[2]), "f"(r.v[3]),
                    "f"(r.v[4]), "f"(r.v[5]), "f"(r.v[6]), "f"(r.v[7])
                 : "memory");
}

__global__ __launch_bounds__(THREADS)
void diag_scale_kernel(const f8* __restrict__ x,
                       const f8* __restrict__ diag,
                       f8* __restrict__ out)
{
    // blockIdx.x = row_block * COL_CHUNKS + col_chunk
    const int col_chunk = blockIdx.x & (COL_CHUNKS - 1);
    const int row_block = blockIdx.x >> 1;              // / COL_CHUNKS

    const int c = col_chunk * THREADS + threadIdx.x;    // v8 column index

    // Diagonal loaded ONCE per thread (two 128-bit cached loads -> 8 regs).
    const float4 d0 = __ldg(&((const float4*)diag)[2 * c + 0]);
    const float4 d1 = __ldg(&((const float4*)diag)[2 * c + 1]);

    const long long base =
        (long long)row_block * ROWS_PER_THREAD * SIZE_V8 + c;

    // Front-batched independent 256-bit loads (512B in flight per thread).
    f8 xv[ROWS_PER_THREAD];
#pragma unroll
    for (int k = 0; k < ROWS_PER_THREAD; k++)
        xv[k] = ldg256_cs(&x[base + (long long)k * SIZE_V8]);

#pragma unroll
    for (int k = 0; k < ROWS_PER_THREAD; k++) {
        f8 ov;
        ov.v[0] = xv[k].v[0] * d0.x;
        ov.v[1] = xv[k].v[1] * d0.y;
        ov.v[2] = xv[k].v[2] * d0.z;
        ov.v[3] = xv[k].v[3] * d0.w;
        ov.v[4] = xv[k].v[4] * d1.x;
        ov.v[5] = xv[k].v[5] * d1.y;
        ov.v[6] = xv[k].v[6] * d1.z;
        ov.v[7] = xv[k].v[7] * d1.w;
        stg256_cs(&out[base + (long long)k * SIZE_V8], ov);
    }
}

extern "C" void kernel_launch(void* const* d_in, const int* in_sizes, int n_in,
                              void* d_out, int out_size)
{
    const f8* x    = (const f8*)d_in[0];
    const f8* diag = (const f8*)d_in[1];
    f8*       out  = (f8*)d_out;

    const int blocks = ROW_BLOCKS * COL_CHUNKS;   // 8192
    diag_scale_kernel<<<blocks, THREADS>>>(x, diag, out);
}